// round 5
// baseline (speedup 1.0000x reference)
#include <cuda_runtime.h>
#include <cuda_bf16.h>
#include <cstdint>

// Problem constants
#define T_TOK   2048        // B*M = 8*256
#define EMB     512
#define UVOC    50000
#define SCALE   20.0f       // 1/TEMPERATURE
#define USPLIT  4
#define UCHUNK  (UVOC / USPLIT)   // 12500

// ---------------- scratch (static device globals; no allocation) ----------
__device__ float g_S[(size_t)T_TOK * UVOC];          // 400 MB: scores, then P in-place
__device__ float g_Q[(size_t)T_TOK * EMB];           // 4 MB: transformed, scaled queries
__device__ float g_part[(size_t)USPLIT * T_TOK * EMB]; // 16 MB: P·V partials

// ---------------- f32x2 helpers ------------------------------------------
__device__ __forceinline__ void fma2(unsigned long long& acc,
                                     unsigned long long a,
                                     unsigned long long b) {
    asm("fma.rn.f32x2 %0, %1, %2, %0;" : "+l"(acc) : "l"(a), "l"(b));
}
__device__ __forceinline__ unsigned long long dup2(float x) {
    unsigned long long r;
    asm("mov.b64 %0, {%1, %1};" : "=l"(r) : "f"(x));
    return r;
}
__device__ __forceinline__ float2 unpack2(unsigned long long v) {
    float2 f;
    asm("mov.b64 {%0, %1}, %2;" : "=f"(f.x), "=f"(f.y) : "l"(v));
    return f;
}

// =========================================================================
// K1: Q[t][f] = SCALE * sum_e src_query_emb[tok[t]][e] * Tm[e][f]
// Block tile 64 tokens x 128 f-cols, e-chunks of 64. 128 threads.
// Pairing over OUTPUT f-columns (Tm rows are f-contiguous).
// =========================================================================
#define K1_SMEM ((64 * 68 + 64 * 132) * 4)

__global__ __launch_bounds__(128)
void k1_prepq(const int* __restrict__ tok,
              const float* __restrict__ qemb,
              const float* __restrict__ Tm) {
    extern __shared__ float sm[];
    float* As = sm;                 // [64][68]  gathered queries (rows=token, cols=e)
    float* Ts = sm + 64 * 68;       // [64][132] Tm chunk (rows=e, cols=f 0..127)
    __shared__ int stok[64];

    const int t0 = blockIdx.x * 64;
    const int f0 = blockIdx.y * 128;
    const int tid = threadIdx.x;
    const int tr = tid >> 4;        // 0..7  token group
    const int tc = tid & 15;        // 0..15 f-pair group

    if (tid < 64) stok[tid] = tok[t0 + tid];

    unsigned long long acc[8][4];
#pragma unroll
    for (int r = 0; r < 8; r++)
#pragma unroll
        for (int c = 0; c < 4; c++) acc[r][c] = 0ULL;

    for (int ec = 0; ec < EMB; ec += 64) {
        __syncthreads();
        // gather queries: 64 rows x 16 float4
#pragma unroll
        for (int k = 0; k < 8; k++) {
            int idx = tid + 128 * k;            // 0..1023
            int row = idx >> 4, c4 = idx & 15;
            float4 v = *(const float4*)&qemb[(size_t)stok[row] * EMB + ec + 4 * c4];
            *(float4*)&As[row * 68 + 4 * c4] = v;
        }
        // Tm chunk: 64 rows x 32 float4
#pragma unroll
        for (int k = 0; k < 16; k++) {
            int idx = tid + 128 * k;            // 0..2047
            int row = idx >> 5, c4 = idx & 31;
            float4 v = *(const float4*)&Tm[(size_t)(ec + row) * EMB + f0 + 4 * c4];
            *(float4*)&Ts[row * 132 + 4 * c4] = v;
        }
        __syncthreads();

#pragma unroll 4
        for (int k = 0; k < 32; k++) {          // 2 e's per step
            unsigned long long aa0[8], aa1[8];
#pragma unroll
            for (int r = 0; r < 8; r++) {
                float2 a2 = *(const float2*)&As[(tr + 8 * r) * 68 + 2 * k];
                aa0[r] = dup2(a2.x);
                aa1[r] = dup2(a2.y);
            }
            unsigned long long b0[4], b1[4];
#pragma unroll
            for (int c = 0; c < 4; c++) {
                b0[c] = *(const unsigned long long*)&Ts[(2 * k) * 132 + 2 * (tc + 16 * c)];
                b1[c] = *(const unsigned long long*)&Ts[(2 * k + 1) * 132 + 2 * (tc + 16 * c)];
            }
#pragma unroll
            for (int r = 0; r < 8; r++)
#pragma unroll
                for (int c = 0; c < 4; c++) {
                    fma2(acc[r][c], aa0[r], b0[c]);
                    fma2(acc[r][c], aa1[r], b1[c]);
                }
        }
    }

#pragma unroll
    for (int r = 0; r < 8; r++)
#pragma unroll
        for (int c = 0; c < 4; c++) {
            float2 v = unpack2(acc[r][c]);
            int t = t0 + tr + 8 * r;
            int f = f0 + 2 * (tc + 16 * c);
            float2 o = make_float2(SCALE * v.x, SCALE * v.y);
            *(float2*)&g_Q[(size_t)t * EMB + f] = o;
        }
}

// =========================================================================
// K2: S[t][u] = dot(Q[t], K[u])   (scale already folded into Q)
// Block tile 64 t x 128 u, e-chunks of 64, 128 threads, 8x8 f32x2 reg tile.
// Reduction paired over contiguous E for both operands.
// =========================================================================
#define K2_SMEM ((64 * 68 + 128 * 68) * 4)

__global__ __launch_bounds__(128)
void k2_scores(const float* __restrict__ kemb) {
    extern __shared__ float sm[];
    float* Qs = sm;                 // [64][68]
    float* Ks = sm + 64 * 68;       // [128][68]

    const int t0 = blockIdx.x * 64;
    const int u0 = blockIdx.y * 128;
    const int tid = threadIdx.x;
    const int tr = tid >> 4;        // 0..7
    const int tc = tid & 15;        // 0..15

    unsigned long long acc[8][8];
#pragma unroll
    for (int r = 0; r < 8; r++)
#pragma unroll
        for (int c = 0; c < 8; c++) acc[r][c] = 0ULL;

    for (int ec = 0; ec < EMB; ec += 64) {
        __syncthreads();
        // Q chunk: 64 rows x 16 float4
#pragma unroll
        for (int k = 0; k < 8; k++) {
            int idx = tid + 128 * k;
            int row = idx >> 4, c4 = idx & 15;
            float4 v = *(const float4*)&g_Q[(size_t)(t0 + row) * EMB + ec + 4 * c4];
            *(float4*)&Qs[row * 68 + 4 * c4] = v;
        }
        // K chunk: 128 rows x 16 float4 (clamp rows past vocab end)
#pragma unroll
        for (int k = 0; k < 16; k++) {
            int idx = tid + 128 * k;
            int row = idx >> 4, c4 = idx & 15;
            int u = u0 + row;
            if (u >= UVOC) u = UVOC - 1;
            float4 v = *(const float4*)&kemb[(size_t)u * EMB + ec + 4 * c4];
            *(float4*)&Ks[row * 68 + 4 * c4] = v;
        }
        __syncthreads();

#pragma unroll 4
        for (int ep = 0; ep < 16; ep++) {       // 4 e's (2 pairs) per step
            ulonglong2 a[8], b[8];
#pragma unroll
            for (int r = 0; r < 8; r++)
                a[r] = *(const ulonglong2*)&Qs[(tr + 8 * r) * 68 + 4 * ep];
#pragma unroll
            for (int c = 0; c < 8; c++)
                b[c] = *(const ulonglong2*)&Ks[(tc + 16 * c) * 68 + 4 * ep];
#pragma unroll
            for (int r = 0; r < 8; r++)
#pragma unroll
                for (int c = 0; c < 8; c++) {
                    fma2(acc[r][c], a[r].x, b[c].x);
                    fma2(acc[r][c], a[r].y, b[c].y);
                }
        }
    }

#pragma unroll
    for (int r = 0; r < 8; r++)
#pragma unroll
        for (int c = 0; c < 8; c++) {
            float2 v = unpack2(acc[r][c]);
            int t = t0 + tr + 8 * r;
            int u = u0 + tc + 16 * c;
            if (u < UVOC) g_S[(size_t)t * UVOC + u] = v.x + v.y;
        }
}

// =========================================================================
// K3: per-row softmax over U, in place: S -> P = exp(S - m) / l
// One block per token row, 256 threads, online max/sum then rewrite.
// =========================================================================
__global__ __launch_bounds__(256)
void k3_softmax() {
    const int t = blockIdx.x;
    float* row = g_S + (size_t)t * UVOC;
    const int tid = threadIdx.x;

    float m = -INFINITY, l = 0.0f;
    // 50000 floats = 12500 float4 exactly
    for (int i = tid; i < UVOC / 4; i += 256) {
        float4 s4 = ((const float4*)row)[i];
        float v[4] = {s4.x, s4.y, s4.z, s4.w};
#pragma unroll
        for (int j = 0; j < 4; j++) {
            float s = v[j];
            if (s > m) { l *= __expf(m - s); m = s; }
            l += __expf(s - m);
        }
    }
    // warp merge
#pragma unroll
    for (int off = 16; off > 0; off >>= 1) {
        float m2 = __shfl_xor_sync(0xffffffffu, m, off);
        float l2 = __shfl_xor_sync(0xffffffffu, l, off);
        float mm = fmaxf(m, m2);
        l = l * __expf(m - mm) + l2 * __expf(m2 - mm);
        m = mm;
    }
    __shared__ float wm[8], wl[8];
    __shared__ float fm, fil;
    const int lane = tid & 31, wid = tid >> 5;
    if (lane == 0) { wm[wid] = m; wl[wid] = l; }
    __syncthreads();
    if (tid == 0) {
        float M = wm[0], L = wl[0];
#pragma unroll
        for (int w = 1; w < 8; w++) {
            float mm = fmaxf(M, wm[w]);
            L = L * __expf(M - mm) + wl[w] * __expf(wm[w] - mm);
            M = mm;
        }
        fm = M;
        fil = 1.0f / L;
    }
    __syncthreads();
    const float bm = fm, bil = fil;

    for (int i = tid; i < UVOC / 4; i += 256) {
        float4 s4 = ((const float4*)row)[i];
        s4.x = __expf(s4.x - bm) * bil;
        s4.y = __expf(s4.y - bm) * bil;
        s4.z = __expf(s4.z - bm) * bil;
        s4.w = __expf(s4.w - bm) * bil;
        ((float4*)row)[i] = s4;
    }
}

// =========================================================================
// K4: part[z][t][e] = sum_{u in z-range} P[t][u] * V[u][e]
// Block tile 64 t x 128 e, u-chunks of 64, 128 threads.
// Pairing over OUTPUT e-columns (V rows are e-contiguous).
// =========================================================================
#define K4_SMEM ((64 * 68 + 64 * 132) * 4)

__global__ __launch_bounds__(128)
void k4_pv(const float* __restrict__ vemb) {
    extern __shared__ float sm[];
    float* Ps = sm;                 // [64][68]  (rows=token, cols=u-chunk)
    float* Vs = sm + 64 * 68;       // [64][132] (rows=u, cols=e 0..127)

    const int t0 = blockIdx.x * 64;
    const int e0 = blockIdx.y * 128;
    const int z  = blockIdx.z;
    const int ubeg = z * UCHUNK;
    const int uend = ubeg + UCHUNK;
    const int tid = threadIdx.x;
    const int tr = tid >> 4;
    const int tc = tid & 15;

    unsigned long long acc[8][4];
#pragma unroll
    for (int r = 0; r < 8; r++)
#pragma unroll
        for (int c = 0; c < 4; c++) acc[r][c] = 0ULL;

    for (int ub = ubeg; ub < uend; ub += 64) {
        __syncthreads();
        // P chunk: 64 rows x 16 float4 (zero-pad past uend; uend % 4 == 0)
#pragma unroll
        for (int k = 0; k < 8; k++) {
            int idx = tid + 128 * k;
            int row = idx >> 4, c4 = idx & 15;
            float4 v;
            if (ub + 4 * c4 < uend)
                v = *(const float4*)&g_S[(size_t)(t0 + row) * UVOC + ub + 4 * c4];
            else
                v = make_float4(0.f, 0.f, 0.f, 0.f);
            *(float4*)&Ps[row * 68 + 4 * c4] = v;
        }
        // V chunk: 64 rows x 32 float4 (clamp rows; padded P is zero anyway)
#pragma unroll
        for (int k = 0; k < 16; k++) {
            int idx = tid + 128 * k;
            int row = idx >> 5, c4 = idx & 31;
            int u = ub + row;
            if (u >= UVOC) u = UVOC - 1;
            float4 v = *(const float4*)&vemb[(size_t)u * EMB + e0 + 4 * c4];
            *(float4*)&Vs[row * 132 + 4 * c4] = v;
        }
        __syncthreads();

#pragma unroll 4
        for (int k = 0; k < 32; k++) {          // 2 u's per step
            unsigned long long aa0[8], aa1[8];
#pragma unroll
            for (int r = 0; r < 8; r++) {
                float2 a2 = *(const float2*)&Ps[(tr + 8 * r) * 68 + 2 * k];
                aa0[r] = dup2(a2.x);
                aa1[r] = dup2(a2.y);
            }
            unsigned long long b0[4], b1[4];
#pragma unroll
            for (int c = 0; c < 4; c++) {
                b0[c] = *(const unsigned long long*)&Vs[(2 * k) * 132 + 2 * (tc + 16 * c)];
                b1[c] = *(const unsigned long long*)&Vs[(2 * k + 1) * 132 + 2 * (tc + 16 * c)];
            }
#pragma unroll
            for (int r = 0; r < 8; r++)
#pragma unroll
                for (int c = 0; c < 4; c++) {
                    fma2(acc[r][c], aa0[r], b0[c]);
                    fma2(acc[r][c], aa1[r], b1[c]);
                }
        }
    }

    float* pbase = g_part + (size_t)z * T_TOK * EMB;
#pragma unroll
    for (int r = 0; r < 8; r++)
#pragma unroll
        for (int c = 0; c < 4; c++) {
            float2 v = unpack2(acc[r][c]);
            int t = t0 + tr + 8 * r;
            int e = e0 + 2 * (tc + 16 * c);
            *(float2*)&pbase[(size_t)t * EMB + e] = v;
        }
}

// =========================================================================
// K5: out[t][e] = alpha[tok[t]] * mono[tok[t]][e] + sum_z part[z][t][e]
// =========================================================================
__global__ __launch_bounds__(128)
void k5_combine(const int* __restrict__ tok,
                const float* __restrict__ memb,
                const float* __restrict__ aemb,
                float* __restrict__ out) {
    const int t = blockIdx.x;
    const int tid = threadIdx.x;            // 128 threads x float4 = 512
    const int tk = tok[t];
    const float al = aemb[tk];

    float4 m4 = *(const float4*)&memb[(size_t)tk * EMB + 4 * tid];
    float4 s = make_float4(0.f, 0.f, 0.f, 0.f);
#pragma unroll
    for (int z = 0; z < USPLIT; z++) {
        float4 p = *(const float4*)&g_part[((size_t)z * T_TOK + t) * EMB + 4 * tid];
        s.x += p.x; s.y += p.y; s.z += p.z; s.w += p.w;
    }
    float4 o;
    o.x = al * m4.x + s.x;
    o.y = al * m4.y + s.y;
    o.z = al * m4.z + s.z;
    o.w = al * m4.w + s.w;
    *(float4*)&out[(size_t)t * EMB + 4 * tid] = o;
}

// =========================================================================
extern "C" void kernel_launch(void* const* d_in, const int* in_sizes, int n_in,
                              void* d_out, int out_size) {
    const int*   tok  = (const int*)d_in[0];
    const float* Tm   = (const float*)d_in[1];
    const float* qemb = (const float*)d_in[2];
    const float* memb = (const float*)d_in[3];
    const float* kemb = (const float*)d_in[4];
    const float* vemb = (const float*)d_in[5];
    const float* aemb = (const float*)d_in[6];
    float* out = (float*)d_out;

    // dynamic smem > 48KB: set attributes (idempotent, host-side, capture-safe)
    cudaFuncSetAttribute(k1_prepq,  cudaFuncAttributeMaxDynamicSharedMemorySize, K1_SMEM);
    cudaFuncSetAttribute(k2_scores, cudaFuncAttributeMaxDynamicSharedMemorySize, K2_SMEM);
    cudaFuncSetAttribute(k4_pv,     cudaFuncAttributeMaxDynamicSharedMemorySize, K4_SMEM);

    // K1: Q = 20 * gather(src_query) @ Tm
    k1_prepq<<<dim3(T_TOK / 64, EMB / 128), 128, K1_SMEM>>>(tok, qemb, Tm);
    // K2: S = Q @ K^T   (grid.y tiles of 128 u; 391 covers 50000 with guard)
    k2_scores<<<dim3(T_TOK / 64, (UVOC + 127) / 128), 128, K2_SMEM>>>(kemb);
    // K3: softmax rows in place -> P
    k3_softmax<<<T_TOK, 256>>>();
    // K4: partial P @ V per u-split
    k4_pv<<<dim3(T_TOK / 64, EMB / 128, USPLIT), 128, K4_SMEM>>>(vemb);
    // K5: combine with alpha * mono
    k5_combine<<<T_TOK, 128>>>(tok, memb, aemb, out);
}

// round 10
// speedup vs baseline: 1.8309x; 1.8309x over previous
#include <cuda_runtime.h>
#include <cuda_bf16.h>
#include <cstdint>

// ---------------- problem constants ----------------
#define T_TOK   2048
#define EMB     512
#define UVOC    50000
#define UPAD    50176            // 392*128
#define SCALE   20.0f
#define KDIM    1536             // 3*EMB (split-concat K for GEMM1)
#define JSEG    50176
#define JPAD    150528           // 3*JSEG (split-concat K for GEMM2)
#define ZSPLIT  8
#define JCH     (JPAD / ZSPLIT)  // 18816
#define NC2     (JCH / 64)       // 294

// ---------------- scratch (static device globals) ----------------
__device__ float          g_S [(size_t)T_TOK * UVOC];     // 400 MB scores
__device__ __nv_bfloat16  g_Qc[(size_t)T_TOK * KDIM];     // [Qh|Qh|Ql]
__device__ __nv_bfloat16  g_Kc[(size_t)UPAD  * KDIM];     // [Kh|Kl|Kh]
__device__ __nv_bfloat16  g_Pc[(size_t)T_TOK * JPAD];     // [Ph|Ph|Pl] (unnormalized)
__device__ __nv_bfloat16  g_VT[(size_t)EMB   * JPAD];     // [Vh|Vl|Vh] transposed
__device__ float          g_part[(size_t)ZSPLIT * T_TOK * EMB];
__device__ float          g_rowm[T_TOK];                  // row max
__device__ float          g_rowl[T_TOK];                  // row sum of exp

// ---------------- helpers ----------------
__device__ __forceinline__ uint32_t su32(const void* p) {
    uint32_t a;
    asm("{ .reg .u64 t; cvta.to.shared.u64 t, %1; cvt.u32.u64 %0, t; }" : "=r"(a) : "l"(p));
    return a;
}

// SW128 swizzle (XOR bits[4:6] with bits[7:9]) — conflict-free ldmatrix + stores
#define SWZ(x) ((x) ^ ((((uint32_t)(x)) >> 3) & 0x70))

// cp.async 16B (sm_80+, valid on compute_103 base target)
__device__ __forceinline__ void cp16(uint32_t dst, const void* src) {
    asm volatile("cp.async.cg.shared.global [%0], [%1], 16;" :: "r"(dst), "l"(src));
}
#define CP_COMMIT() asm volatile("cp.async.commit_group;" ::: "memory")
#define CP_WAIT1()  asm volatile("cp.async.wait_group 1;" ::: "memory")
#define CP_WAIT0()  asm volatile("cp.async.wait_group 0;" ::: "memory")

__device__ __forceinline__ void ldsm4(uint32_t& r0, uint32_t& r1, uint32_t& r2, uint32_t& r3,
                                      uint32_t addr) {
    asm volatile("ldmatrix.sync.aligned.m8n8.x4.shared.b16 {%0,%1,%2,%3}, [%4];"
                 : "=r"(r0), "=r"(r1), "=r"(r2), "=r"(r3) : "r"(addr));
}
__device__ __forceinline__ void mma16816(float* c,
                                         uint32_t a0, uint32_t a1, uint32_t a2, uint32_t a3,
                                         uint32_t b0, uint32_t b1) {
    asm volatile("mma.sync.aligned.m16n8k16.row.col.f32.bf16.bf16.f32 "
                 "{%0,%1,%2,%3}, {%4,%5,%6,%7}, {%8,%9}, {%0,%1,%2,%3};"
                 : "+f"(c[0]), "+f"(c[1]), "+f"(c[2]), "+f"(c[3])
                 : "r"(a0), "r"(a1), "r"(a2), "r"(a3), "r"(b0), "r"(b1));
}

// fp32 -> bf16 hi/lo split
__device__ __forceinline__ void split32(float x, __nv_bfloat16& h, __nv_bfloat16& l) {
    h = __float2bfloat16(x);
    l = __float2bfloat16(x - __bfloat162float(h));
}

// FMA-only exp(x) for x <= 0 (avoids MUFU wall). |err| ~1e-7 rel.
__device__ __forceinline__ float exp_fma(float x) {
    float y = fmaxf(x * 1.44269504088896f, -120.0f);
    float fn = rintf(y);
    float r = y - fn;
    float p = 1.33336624e-3f;
    p = fmaf(p, r, 9.61800651e-3f);
    p = fmaf(p, r, 5.55036329e-2f);
    p = fmaf(p, r, 2.40226507e-1f);
    p = fmaf(p, r, 6.93147182e-1f);
    p = fmaf(p, r, 1.0f);
    int n = (int)fn;
    float sc = __int_as_float((n + 127) << 23);
    return p * sc;
}

// ---------------- f32x2 helpers (K1 SIMT prologue) ----------------
__device__ __forceinline__ void fma2(unsigned long long& acc,
                                     unsigned long long a, unsigned long long b) {
    asm("fma.rn.f32x2 %0, %1, %2, %0;" : "+l"(acc) : "l"(a), "l"(b));
}
__device__ __forceinline__ unsigned long long dup2(float x) {
    unsigned long long r;
    asm("mov.b64 %0, {%1, %1};" : "=l"(r) : "f"(x));
    return r;
}
__device__ __forceinline__ float2 unpack2(unsigned long long v) {
    float2 f;
    asm("mov.b64 {%0, %1}, %2;" : "=f"(f.x), "=f"(f.y) : "l"(v));
    return f;
}

// =========================================================================
// K1: q = 20 * gather(src_query) @ Tm  -> split-concat Qc = [Qh|Qh|Ql]
// =========================================================================
#define K1_SMEM ((64 * 68 + 64 * 132) * 4)

__global__ __launch_bounds__(128)
void k1_prepq(const int* __restrict__ tok,
              const float* __restrict__ qemb,
              const float* __restrict__ Tm) {
    extern __shared__ float sm[];
    float* As = sm;
    float* Ts = sm + 64 * 68;
    __shared__ int stok[64];

    const int t0 = blockIdx.x * 64;
    const int f0 = blockIdx.y * 128;
    const int tid = threadIdx.x;
    const int tr = tid >> 4;
    const int tc = tid & 15;

    if (tid < 64) stok[tid] = tok[t0 + tid];

    unsigned long long acc[8][4];
#pragma unroll
    for (int r = 0; r < 8; r++)
#pragma unroll
        for (int c = 0; c < 4; c++) acc[r][c] = 0ULL;

    for (int ec = 0; ec < EMB; ec += 64) {
        __syncthreads();
#pragma unroll
        for (int k = 0; k < 8; k++) {
            int idx = tid + 128 * k;
            int row = idx >> 4, c4 = idx & 15;
            float4 v = *(const float4*)&qemb[(size_t)stok[row] * EMB + ec + 4 * c4];
            *(float4*)&As[row * 68 + 4 * c4] = v;
        }
#pragma unroll
        for (int k = 0; k < 16; k++) {
            int idx = tid + 128 * k;
            int row = idx >> 5, c4 = idx & 31;
            float4 v = *(const float4*)&Tm[(size_t)(ec + row) * EMB + f0 + 4 * c4];
            *(float4*)&Ts[row * 132 + 4 * c4] = v;
        }
        __syncthreads();

#pragma unroll 4
        for (int k = 0; k < 32; k++) {
            unsigned long long aa0[8], aa1[8];
#pragma unroll
            for (int r = 0; r < 8; r++) {
                float2 a2 = *(const float2*)&As[(tr + 8 * r) * 68 + 2 * k];
                aa0[r] = dup2(a2.x);
                aa1[r] = dup2(a2.y);
            }
            unsigned long long b0[4], b1[4];
#pragma unroll
            for (int c = 0; c < 4; c++) {
                b0[c] = *(const unsigned long long*)&Ts[(2 * k) * 132 + 2 * (tc + 16 * c)];
                b1[c] = *(const unsigned long long*)&Ts[(2 * k + 1) * 132 + 2 * (tc + 16 * c)];
            }
#pragma unroll
            for (int r = 0; r < 8; r++)
#pragma unroll
                for (int c = 0; c < 4; c++) {
                    fma2(acc[r][c], aa0[r], b0[c]);
                    fma2(acc[r][c], aa1[r], b1[c]);
                }
        }
    }

#pragma unroll
    for (int r = 0; r < 8; r++)
#pragma unroll
        for (int c = 0; c < 4; c++) {
            float2 v = unpack2(acc[r][c]);
            float a0 = SCALE * v.x, a1 = SCALE * v.y;
            __nv_bfloat16 h0, l0, h1, l1;
            split32(a0, h0, l0);
            split32(a1, h1, l1);
            int t = t0 + tr + 8 * r;
            int f = f0 + 2 * (tc + 16 * c);
            __nv_bfloat16* row = g_Qc + (size_t)t * KDIM;
            __nv_bfloat162 hh; hh.x = h0; hh.y = h1;
            __nv_bfloat162 ll; ll.x = l0; ll.y = l1;
            *(__nv_bfloat162*)(row + f) = hh;
            *(__nv_bfloat162*)(row + EMB + f) = hh;
            *(__nv_bfloat162*)(row + 2 * EMB + f) = ll;
        }
}

// =========================================================================
// convK: Kc = [Kh|Kl|Kh] (rows padded to UPAD with zeros)
// =========================================================================
__global__ __launch_bounds__(256)
void k_convK(const float* __restrict__ kemb) {
    int idx = blockIdx.x * 256 + threadIdx.x;
    if (idx >= UPAD * (EMB / 4)) return;
    int u = idx / (EMB / 4);
    int e = (idx % (EMB / 4)) * 4;
    float4 v = (u < UVOC) ? *(const float4*)&kemb[(size_t)u * EMB + e]
                          : make_float4(0.f, 0.f, 0.f, 0.f);
    __nv_bfloat16 h0, l0, h1, l1, h2, l2, h3, l3;
    split32(v.x, h0, l0); split32(v.y, h1, l1);
    split32(v.z, h2, l2); split32(v.w, h3, l3);
    __nv_bfloat162 ha; ha.x = h0; ha.y = h1;
    __nv_bfloat162 hb; hb.x = h2; hb.y = h3;
    __nv_bfloat162 la; la.x = l0; la.y = l1;
    __nv_bfloat162 lb; lb.x = l2; lb.y = l3;
    __nv_bfloat16* row = g_Kc + (size_t)u * KDIM;
    *(__nv_bfloat162*)(row + e) = ha;
    *(__nv_bfloat162*)(row + e + 2) = hb;
    *(__nv_bfloat162*)(row + EMB + e) = la;
    *(__nv_bfloat162*)(row + EMB + e + 2) = lb;
    *(__nv_bfloat162*)(row + 2 * EMB + e) = ha;
    *(__nv_bfloat162*)(row + 2 * EMB + e + 2) = hb;
}

// =========================================================================
// convV: VT[e][j] = [Vh|Vl|Vh] transposed (u-padded with zeros)
// =========================================================================
__global__ __launch_bounds__(256)
void k_convV(const float* __restrict__ vemb) {
    __shared__ float tile[64][65];
    const int u0 = blockIdx.x * 64;
    const int e0 = blockIdx.y * 64;
    const int tid = threadIdx.x;

#pragma unroll
    for (int i = 0; i < 4; i++) {
        int idx = tid + 256 * i;
        int r = idx >> 4, q = idx & 15;
        int u = u0 + r;
        float4 v = (u < UVOC) ? *(const float4*)&vemb[(size_t)u * EMB + e0 + 4 * q]
                              : make_float4(0.f, 0.f, 0.f, 0.f);
        tile[r][4 * q + 0] = v.x; tile[r][4 * q + 1] = v.y;
        tile[r][4 * q + 2] = v.z; tile[r][4 * q + 3] = v.w;
    }
    __syncthreads();

#pragma unroll
    for (int i = 0; i < 8; i++) {
        int idx = tid + 256 * i;
        int er = idx >> 5, up = idx & 31;
        float a = tile[2 * up][er];
        float b = tile[2 * up + 1][er];
        __nv_bfloat16 ha, la, hb, lb;
        split32(a, ha, la);
        split32(b, hb, lb);
        __nv_bfloat162 hh; hh.x = ha; hh.y = hb;
        __nv_bfloat162 ll; ll.x = la; ll.y = lb;
        __nv_bfloat16* row = g_VT + (size_t)(e0 + er) * JPAD + u0 + 2 * up;
        *(__nv_bfloat162*)(row) = hh;
        *(__nv_bfloat162*)(row + JSEG) = ll;
        *(__nv_bfloat162*)(row + 2 * JSEG) = hh;
    }
}

// =========================================================================
// mma.sync GEMM: C[128 x 128] = A[128 x K] * B[128 x K]^T, bf16, K-chunk 64,
// 2-stage cp.async pipeline, SW128 smem, 8 warps (4M x 2N), warp tile 32x64.
// MODE 0: S = Qc * Kc^T -> g_S (fp32, u-guarded)
// MODE 1: part[z] = Pc * VT^T -> g_part
// =========================================================================
#define STAGE_B 32768                    // 16KB A + 16KB B per stage
#define GSM     (2 * STAGE_B + 1024)

template <int MODE>
__global__ __launch_bounds__(256)
void k_gemm() {
    constexpr int LD  = (MODE == 0) ? KDIM : JPAD;
    constexpr int NCH = (MODE == 0) ? (KDIM / 64) : NC2;

    extern __shared__ char dsm_raw[];
    const int tid = threadIdx.x;
    const int wid = tid >> 5;
    const int lane = tid & 31;

    const int t0 = blockIdx.x * 128;
    const int n0 = blockIdx.y * 128;
    const int kbeg = (MODE == 0) ? 0 : (blockIdx.z * JCH);

    const __nv_bfloat16* Abase = (MODE == 0 ? g_Qc : g_Pc) + (size_t)t0 * LD + kbeg;
    const __nv_bfloat16* Bbase = (MODE == 0 ? g_Kc : g_VT) + (size_t)n0 * LD + kbeg;

    const uint32_t raw = su32(dsm_raw);
    const uint32_t sbase = (raw + 1023u) & ~1023u;

    const int wm = (wid & 3) * 32;       // warp M offset in tile
    const int wn = (wid >> 2) * 64;      // warp N offset in tile

    float acc[2][8][4];
#pragma unroll
    for (int mi = 0; mi < 2; mi++)
#pragma unroll
        for (int ni = 0; ni < 8; ni++)
#pragma unroll
            for (int q = 0; q < 4; q++) acc[mi][ni][q] = 0.0f;

    // ---- async copy of chunk c into stage (c & 1) ----
    auto issue = [&](int c) {
        const int s = c & 1;
        const uint32_t dA = sbase + s * STAGE_B;
        const uint32_t dB = dA + 16384;
        const int r = tid >> 1;                    // 0..127 (2 threads per row)
        const int q = (tid & 1) * 4;               // q, q+1, q+2, q+3 (16B each)
        const __nv_bfloat16* srcA = Abase + (size_t)r * LD + c * 64 + q * 8;
        const __nv_bfloat16* srcB = Bbase + (size_t)r * LD + c * 64 + q * 8;
#pragma unroll
        for (int j = 0; j < 4; j++) {
            cp16(dA + SWZ(r * 128 + (q + j) * 16), srcA + j * 8);
            cp16(dB + SWZ(r * 128 + (q + j) * 16), srcB + j * 8);
        }
        CP_COMMIT();
    };

    issue(0);
    if (NCH > 1) issue(1);

    for (int c = 0; c < NCH; c++) {
        if (c + 1 < NCH) CP_WAIT1(); else CP_WAIT0();
        __syncthreads();

        const int s = c & 1;
        const uint32_t A = sbase + s * STAGE_B;
        const uint32_t B = A + 16384;

#pragma unroll
        for (int ks = 0; ks < 4; ks++) {
            // A frags: 2 x ldmatrix.x4 (m16k16 each)
            uint32_t a[2][4];
#pragma unroll
            for (int mi = 0; mi < 2; mi++) {
                int row = wm + 16 * mi + (lane & 15);
                int col = ks * 16 + (lane >> 4) * 8;
                ldsm4(a[mi][0], a[mi][1], a[mi][2], a[mi][3],
                      A + SWZ(row * 128 + col * 2));
            }
            // B frags: 4 x ldmatrix.x4, each covers n16 x k16
#pragma unroll
            for (int ni = 0; ni < 4; ni++) {
                uint32_t b0, b1, b2, b3;
                int g = lane >> 3;                 // 0..3
                int row = wn + 16 * ni + (lane & 7) + ((g >> 1) * 8);
                int col = ks * 16 + (g & 1) * 8;
                ldsm4(b0, b1, b2, b3, B + SWZ(row * 128 + col * 2));
#pragma unroll
                for (int mi = 0; mi < 2; mi++) {
                    mma16816(acc[mi][2 * ni],     a[mi][0], a[mi][1], a[mi][2], a[mi][3], b0, b1);
                    mma16816(acc[mi][2 * ni + 1], a[mi][0], a[mi][1], a[mi][2], a[mi][3], b2, b3);
                }
            }
        }
        __syncthreads();
        if (c + 2 < NCH) issue(c + 2);
    }

    // ---- epilogue: fragment layout m = t/4 (+8), n = 2*(t%4) ----
#pragma unroll
    for (int mi = 0; mi < 2; mi++)
#pragma unroll
        for (int ni = 0; ni < 8; ni++) {
            int m = t0 + wm + 16 * mi + (lane >> 2);
            int n = n0 + wn + 8 * ni + 2 * (lane & 3);
            float2 lo = make_float2(acc[mi][ni][0], acc[mi][ni][1]);
            float2 hi = make_float2(acc[mi][ni][2], acc[mi][ni][3]);
            if (MODE == 0) {
                if (n < UVOC) {
                    *(float2*)&g_S[(size_t)m * UVOC + n] = lo;
                    *(float2*)&g_S[(size_t)(m + 8) * UVOC + n] = hi;
                }
            } else {
                float* base = g_part + (size_t)blockIdx.z * T_TOK * EMB;
                *(float2*)&base[(size_t)m * EMB + n] = lo;
                *(float2*)&base[(size_t)(m + 8) * EMB + n] = hi;
            }
        }
}

// =========================================================================
// K3a: row max (pure fmax pass — no MUFU)
// =========================================================================
__global__ __launch_bounds__(256)
void k3a_max() {
    const int t = blockIdx.x;
    const float* row = g_S + (size_t)t * UVOC;
    const int tid = threadIdx.x;

    float m = -1e30f;
    for (int i = tid; i < UVOC / 4; i += 256) {
        float4 s4 = ((const float4*)row)[i];
        m = fmaxf(m, fmaxf(fmaxf(s4.x, s4.y), fmaxf(s4.z, s4.w)));
    }
#pragma unroll
    for (int off = 16; off > 0; off >>= 1)
        m = fmaxf(m, __shfl_xor_sync(0xffffffffu, m, off));
    __shared__ float wm[8];
    if ((tid & 31) == 0) wm[tid >> 5] = m;
    __syncthreads();
    if (tid == 0) {
        float M = wm[0];
#pragma unroll
        for (int w = 1; w < 8; w++) M = fmaxf(M, wm[w]);
        g_rowm[t] = M;
    }
}

// =========================================================================
// K3b: Pc = split(exp(S - m)) unnormalized; row sum -> g_rowl.
// =========================================================================
__global__ __launch_bounds__(256)
void k3b_exp() {
    const int t = blockIdx.x;
    const float* row = g_S + (size_t)t * UVOC;
    const int tid = threadIdx.x;
    const float bm = g_rowm[t];

    __nv_bfloat16* prow = g_Pc + (size_t)t * JPAD;
    float l = 0.0f;
    for (int i = tid; i < UVOC / 4; i += 256) {
        float4 s4 = ((const float4*)row)[i];
        float p0 = exp_fma(s4.x - bm);
        float p1 = exp_fma(s4.y - bm);
        float p2 = exp_fma(s4.z - bm);
        float p3 = exp_fma(s4.w - bm);
        l += (p0 + p1) + (p2 + p3);
        __nv_bfloat16 h0, l0, h1, l1, h2, l2, h3, l3;
        split32(p0, h0, l0); split32(p1, h1, l1);
        split32(p2, h2, l2); split32(p3, h3, l3);
        __nv_bfloat162 ha; ha.x = h0; ha.y = h1;
        __nv_bfloat162 hb; hb.x = h2; hb.y = h3;
        __nv_bfloat162 la; la.x = l0; la.y = l1;
        __nv_bfloat162 lb; lb.x = l2; lb.y = l3;
        int u = 4 * i;
        *(__nv_bfloat162*)(prow + u) = ha;
        *(__nv_bfloat162*)(prow + u + 2) = hb;
        *(__nv_bfloat162*)(prow + JSEG + u) = ha;
        *(__nv_bfloat162*)(prow + JSEG + u + 2) = hb;
        *(__nv_bfloat162*)(prow + 2 * JSEG + u) = la;
        *(__nv_bfloat162*)(prow + 2 * JSEG + u + 2) = lb;
    }
    // zero pad u in [UVOC, UPAD)
    __nv_bfloat162 z2; z2.x = __float2bfloat16(0.f); z2.y = __float2bfloat16(0.f);
    for (int u = UVOC + 2 * tid; u < UPAD; u += 512) {
        *(__nv_bfloat162*)(prow + u) = z2;
        *(__nv_bfloat162*)(prow + JSEG + u) = z2;
        *(__nv_bfloat162*)(prow + 2 * JSEG + u) = z2;
    }

#pragma unroll
    for (int off = 16; off > 0; off >>= 1)
        l += __shfl_xor_sync(0xffffffffu, l, off);
    __shared__ float wl[8];
    if ((tid & 31) == 0) wl[tid >> 5] = l;
    __syncthreads();
    if (tid == 0) {
        float L = wl[0];
#pragma unroll
        for (int w = 1; w < 8; w++) L += wl[w];
        g_rowl[t] = L;
    }
}

// =========================================================================
// K5: out = alpha*mono + (sum_z part[z]) / l[t]
// =========================================================================
__global__ __launch_bounds__(128)
void k5_combine(const int* __restrict__ tok,
                const float* __restrict__ memb,
                const float* __restrict__ aemb,
                float* __restrict__ out) {
    const int t = blockIdx.x;
    const int tid = threadIdx.x;
    const int tk = tok[t];
    const float al = aemb[tk];
    const float inv = 1.0f / g_rowl[t];

    float4 m4 = *(const float4*)&memb[(size_t)tk * EMB + 4 * tid];
    float4 s = make_float4(0.f, 0.f, 0.f, 0.f);
#pragma unroll
    for (int z = 0; z < ZSPLIT; z++) {
        float4 p = *(const float4*)&g_part[((size_t)z * T_TOK + t) * EMB + 4 * tid];
        s.x += p.x; s.y += p.y; s.z += p.z; s.w += p.w;
    }
    float4 o;
    o.x = al * m4.x + s.x * inv;
    o.y = al * m4.y + s.y * inv;
    o.z = al * m4.z + s.z * inv;
    o.w = al * m4.w + s.w * inv;
    *(float4*)&out[(size_t)t * EMB + 4 * tid] = o;
}

// =========================================================================
extern "C" void kernel_launch(void* const* d_in, const int* in_sizes, int n_in,
                              void* d_out, int out_size) {
    const int*   tok  = (const int*)d_in[0];
    const float* Tm   = (const float*)d_in[1];
    const float* qemb = (const float*)d_in[2];
    const float* memb = (const float*)d_in[3];
    const float* kemb = (const float*)d_in[4];
    const float* vemb = (const float*)d_in[5];
    const float* aemb = (const float*)d_in[6];
    float* out = (float*)d_out;

    cudaFuncSetAttribute(k1_prepq,  cudaFuncAttributeMaxDynamicSharedMemorySize, K1_SMEM);
    cudaFuncSetAttribute(k_gemm<0>, cudaFuncAttributeMaxDynamicSharedMemorySize, GSM);
    cudaFuncSetAttribute(k_gemm<1>, cudaFuncAttributeMaxDynamicSharedMemorySize, GSM);

    // prologue: query transform + bf16 split/concat tables
    k1_prepq<<<dim3(T_TOK / 64, EMB / 128), 128, K1_SMEM>>>(tok, qemb, Tm);
    k_convK<<<(UPAD * (EMB / 4) + 255) / 256, 256>>>(kemb);
    k_convV<<<dim3(UPAD / 64, EMB / 64), 256>>>(vemb);

    // GEMM1: S = Qc * Kc^T (x fastest = t-tiles -> Kc tile L2 co-residency)
    k_gemm<0><<<dim3(T_TOK / 128, UPAD / 128), 256, GSM>>>();

    // softmax: max pass, then exp + split (unnormalized)
    k3a_max<<<T_TOK, 256>>>();
    k3b_exp<<<T_TOK, 256>>>();

    // GEMM2: part[z] = Pc * VT^T
    k_gemm<1><<<dim3(T_TOK / 128, EMB / 128, ZSPLIT), 256, GSM>>>();

    // combine (normalize here)
    k5_combine<<<T_TOK, 128>>>(tok, memb, aemb, out);
}

// round 16
// speedup vs baseline: 1.9453x; 1.0625x over previous
#include <cuda_runtime.h>
#include <cuda_bf16.h>
#include <cstdint>

// ---------------- problem constants ----------------
#define T_TOK   2048
#define EMB     512
#define UVOC    50000
#define UPAD    50176            // 392*128
#define SCALE   20.0f
#define KDIM    1536             // 3*EMB (split-concat K for GEMM1)
#define JSEG    50176
#define JPAD    150528           // 3*JSEG (split-concat K for GEMM2)
#define ZSPLIT  8
#define JCH     (JPAD / ZSPLIT)  // 18816
#define NC2     (JCH / 64)       // 294

// ---------------- scratch (static device globals) ----------------
__device__ float          g_S [(size_t)T_TOK * UVOC];     // 400 MB scores
__device__ __nv_bfloat16  g_Qc[(size_t)T_TOK * KDIM];     // [Qh|Qh|Ql]
__device__ __nv_bfloat16  g_Kc[(size_t)UPAD  * KDIM];     // [Kh|Kl|Kh]
__device__ __nv_bfloat16  g_Pc[(size_t)T_TOK * JPAD];     // [Ph|Ph|Pl] (unnormalized)
__device__ __nv_bfloat16  g_VT[(size_t)EMB   * JPAD];     // [Vh|Vl|Vh] transposed
__device__ float          g_part[(size_t)ZSPLIT * T_TOK * EMB];
__device__ float          g_rowm[T_TOK];                  // row max
__device__ float          g_rowl[T_TOK];                  // row sum of exp

// ---------------- helpers ----------------
__device__ __forceinline__ uint32_t su32(const void* p) {
    uint32_t a;
    asm("{ .reg .u64 t; cvta.to.shared.u64 t, %1; cvt.u32.u64 %0, t; }" : "=r"(a) : "l"(p));
    return a;
}

// SW128 swizzle (XOR bits[4:6] with bits[7:9]) — conflict-free ldmatrix + stores
#define SWZ(x) ((x) ^ ((((uint32_t)(x)) >> 3) & 0x70))

// cp.async 16B (sm_80+, valid on compute_103 base target)
__device__ __forceinline__ void cp16(uint32_t dst, const void* src) {
    asm volatile("cp.async.cg.shared.global [%0], [%1], 16;" :: "r"(dst), "l"(src));
}
#define CP_COMMIT() asm volatile("cp.async.commit_group;" ::: "memory")
#define CP_WAIT1()  asm volatile("cp.async.wait_group 1;" ::: "memory")
#define CP_WAIT0()  asm volatile("cp.async.wait_group 0;" ::: "memory")

__device__ __forceinline__ void ldsm4(uint32_t& r0, uint32_t& r1, uint32_t& r2, uint32_t& r3,
                                      uint32_t addr) {
    asm volatile("ldmatrix.sync.aligned.m8n8.x4.shared.b16 {%0,%1,%2,%3}, [%4];"
                 : "=r"(r0), "=r"(r1), "=r"(r2), "=r"(r3) : "r"(addr));
}
__device__ __forceinline__ void mma16816(float* c,
                                         uint32_t a0, uint32_t a1, uint32_t a2, uint32_t a3,
                                         uint32_t b0, uint32_t b1) {
    asm volatile("mma.sync.aligned.m16n8k16.row.col.f32.bf16.bf16.f32 "
                 "{%0,%1,%2,%3}, {%4,%5,%6,%7}, {%8,%9}, {%0,%1,%2,%3};"
                 : "+f"(c[0]), "+f"(c[1]), "+f"(c[2]), "+f"(c[3])
                 : "r"(a0), "r"(a1), "r"(a2), "r"(a3), "r"(b0), "r"(b1));
}

// fp32 -> bf16 hi/lo split
__device__ __forceinline__ void split32(float x, __nv_bfloat16& h, __nv_bfloat16& l) {
    h = __float2bfloat16(x);
    l = __float2bfloat16(x - __bfloat162float(h));
}

// FMA-only exp(x) for x <= 0 (avoids MUFU wall). |err| ~1e-7 rel.
__device__ __forceinline__ float exp_fma(float x) {
    float y = fmaxf(x * 1.44269504088896f, -120.0f);
    float fn = rintf(y);
    float r = y - fn;
    float p = 1.33336624e-3f;
    p = fmaf(p, r, 9.61800651e-3f);
    p = fmaf(p, r, 5.55036329e-2f);
    p = fmaf(p, r, 2.40226507e-1f);
    p = fmaf(p, r, 6.93147182e-1f);
    p = fmaf(p, r, 1.0f);
    int n = (int)fn;
    float sc = __int_as_float((n + 127) << 23);
    return p * sc;
}

// ---------------- f32x2 helpers (K1 SIMT prologue) ----------------
__device__ __forceinline__ void fma2(unsigned long long& acc,
                                     unsigned long long a, unsigned long long b) {
    asm("fma.rn.f32x2 %0, %1, %2, %0;" : "+l"(acc) : "l"(a), "l"(b));
}
__device__ __forceinline__ unsigned long long dup2(float x) {
    unsigned long long r;
    asm("mov.b64 %0, {%1, %1};" : "=l"(r) : "f"(x));
    return r;
}
__device__ __forceinline__ float2 unpack2(unsigned long long v) {
    float2 f;
    asm("mov.b64 {%0, %1}, %2;" : "=f"(f.x), "=f"(f.y) : "l"(v));
    return f;
}

// =========================================================================
// K1: q = 20 * gather(src_query) @ Tm  -> split-concat Qc = [Qh|Qh|Ql]
// =========================================================================
#define K1_SMEM ((64 * 68 + 64 * 132) * 4)

__global__ __launch_bounds__(128)
void k1_prepq(const int* __restrict__ tok,
              const float* __restrict__ qemb,
              const float* __restrict__ Tm) {
    extern __shared__ float sm[];
    float* As = sm;
    float* Ts = sm + 64 * 68;
    __shared__ int stok[64];

    const int t0 = blockIdx.x * 64;
    const int f0 = blockIdx.y * 128;
    const int tid = threadIdx.x;
    const int tr = tid >> 4;
    const int tc = tid & 15;

    if (tid < 64) stok[tid] = tok[t0 + tid];

    unsigned long long acc[8][4];
#pragma unroll
    for (int r = 0; r < 8; r++)
#pragma unroll
        for (int c = 0; c < 4; c++) acc[r][c] = 0ULL;

    for (int ec = 0; ec < EMB; ec += 64) {
        __syncthreads();
#pragma unroll
        for (int k = 0; k < 8; k++) {
            int idx = tid + 128 * k;
            int row = idx >> 4, c4 = idx & 15;
            float4 v = *(const float4*)&qemb[(size_t)stok[row] * EMB + ec + 4 * c4];
            *(float4*)&As[row * 68 + 4 * c4] = v;
        }
#pragma unroll
        for (int k = 0; k < 16; k++) {
            int idx = tid + 128 * k;
            int row = idx >> 5, c4 = idx & 31;
            float4 v = *(const float4*)&Tm[(size_t)(ec + row) * EMB + f0 + 4 * c4];
            *(float4*)&Ts[row * 132 + 4 * c4] = v;
        }
        __syncthreads();

#pragma unroll 4
        for (int k = 0; k < 32; k++) {
            unsigned long long aa0[8], aa1[8];
#pragma unroll
            for (int r = 0; r < 8; r++) {
                float2 a2 = *(const float2*)&As[(tr + 8 * r) * 68 + 2 * k];
                aa0[r] = dup2(a2.x);
                aa1[r] = dup2(a2.y);
            }
            unsigned long long b0[4], b1[4];
#pragma unroll
            for (int c = 0; c < 4; c++) {
                b0[c] = *(const unsigned long long*)&Ts[(2 * k) * 132 + 2 * (tc + 16 * c)];
                b1[c] = *(const unsigned long long*)&Ts[(2 * k + 1) * 132 + 2 * (tc + 16 * c)];
            }
#pragma unroll
            for (int r = 0; r < 8; r++)
#pragma unroll
                for (int c = 0; c < 4; c++) {
                    fma2(acc[r][c], aa0[r], b0[c]);
                    fma2(acc[r][c], aa1[r], b1[c]);
                }
        }
    }

#pragma unroll
    for (int r = 0; r < 8; r++)
#pragma unroll
        for (int c = 0; c < 4; c++) {
            float2 v = unpack2(acc[r][c]);
            float a0 = SCALE * v.x, a1 = SCALE * v.y;
            __nv_bfloat16 h0, l0, h1, l1;
            split32(a0, h0, l0);
            split32(a1, h1, l1);
            int t = t0 + tr + 8 * r;
            int f = f0 + 2 * (tc + 16 * c);
            __nv_bfloat16* row = g_Qc + (size_t)t * KDIM;
            __nv_bfloat162 hh; hh.x = h0; hh.y = h1;
            __nv_bfloat162 ll; ll.x = l0; ll.y = l1;
            *(__nv_bfloat162*)(row + f) = hh;
            *(__nv_bfloat162*)(row + EMB + f) = hh;
            *(__nv_bfloat162*)(row + 2 * EMB + f) = ll;
        }
}

// =========================================================================
// convK: Kc = [Kh|Kl|Kh] (rows padded to UPAD with zeros)
// =========================================================================
__global__ __launch_bounds__(256)
void k_convK(const float* __restrict__ kemb) {
    int idx = blockIdx.x * 256 + threadIdx.x;
    if (idx >= UPAD * (EMB / 4)) return;
    int u = idx / (EMB / 4);
    int e = (idx % (EMB / 4)) * 4;
    float4 v = (u < UVOC) ? *(const float4*)&kemb[(size_t)u * EMB + e]
                          : make_float4(0.f, 0.f, 0.f, 0.f);
    __nv_bfloat16 h0, l0, h1, l1, h2, l2, h3, l3;
    split32(v.x, h0, l0); split32(v.y, h1, l1);
    split32(v.z, h2, l2); split32(v.w, h3, l3);
    __nv_bfloat162 ha; ha.x = h0; ha.y = h1;
    __nv_bfloat162 hb; hb.x = h2; hb.y = h3;
    __nv_bfloat162 la; la.x = l0; la.y = l1;
    __nv_bfloat162 lb; lb.x = l2; lb.y = l3;
    __nv_bfloat16* row = g_Kc + (size_t)u * KDIM;
    *(__nv_bfloat162*)(row + e) = ha;
    *(__nv_bfloat162*)(row + e + 2) = hb;
    *(__nv_bfloat162*)(row + EMB + e) = la;
    *(__nv_bfloat162*)(row + EMB + e + 2) = lb;
    *(__nv_bfloat162*)(row + 2 * EMB + e) = ha;
    *(__nv_bfloat162*)(row + 2 * EMB + e + 2) = hb;
}

// =========================================================================
// convV: VT[e][j] = [Vh|Vl|Vh] transposed (u-padded with zeros)
// =========================================================================
__global__ __launch_bounds__(256)
void k_convV(const float* __restrict__ vemb) {
    __shared__ float tile[64][65];
    const int u0 = blockIdx.x * 64;
    const int e0 = blockIdx.y * 64;
    const int tid = threadIdx.x;

#pragma unroll
    for (int i = 0; i < 4; i++) {
        int idx = tid + 256 * i;
        int r = idx >> 4, q = idx & 15;
        int u = u0 + r;
        float4 v = (u < UVOC) ? *(const float4*)&vemb[(size_t)u * EMB + e0 + 4 * q]
                              : make_float4(0.f, 0.f, 0.f, 0.f);
        tile[r][4 * q + 0] = v.x; tile[r][4 * q + 1] = v.y;
        tile[r][4 * q + 2] = v.z; tile[r][4 * q + 3] = v.w;
    }
    __syncthreads();

#pragma unroll
    for (int i = 0; i < 8; i++) {
        int idx = tid + 256 * i;
        int er = idx >> 5, up = idx & 31;
        float a = tile[2 * up][er];
        float b = tile[2 * up + 1][er];
        __nv_bfloat16 ha, la, hb, lb;
        split32(a, ha, la);
        split32(b, hb, lb);
        __nv_bfloat162 hh; hh.x = ha; hh.y = hb;
        __nv_bfloat162 ll; ll.x = la; ll.y = lb;
        __nv_bfloat16* row = g_VT + (size_t)(e0 + er) * JPAD + u0 + 2 * up;
        *(__nv_bfloat162*)(row) = hh;
        *(__nv_bfloat162*)(row + JSEG) = ll;
        *(__nv_bfloat162*)(row + 2 * JSEG) = hh;
    }
}

// =========================================================================
// mma.sync GEMM: C[128 x 128] = A[128 x K] * B[128 x K]^T, bf16, K-chunk 64,
// 3-stage cp.async pipeline (copy overlaps MMA), one barrier per chunk,
// SW128 smem, 8 warps (4M x 2N), warp tile 32x64, grouped ldmatrix batches.
// MODE 0: S = Qc * Kc^T -> g_S (fp32, u-guarded)
// MODE 1: part[z] = Pc * VT^T -> g_part
// =========================================================================
#define STAGE_B 32768                    // 16KB A + 16KB B per stage
#define NSTAGE  3
#define GSM     (NSTAGE * STAGE_B + 1024)

template <int MODE>
__global__ __launch_bounds__(256)
void k_gemm() {
    constexpr int LD  = (MODE == 0) ? KDIM : JPAD;
    constexpr int NCH = (MODE == 0) ? (KDIM / 64) : NC2;

    extern __shared__ char dsm_raw[];
    const int tid = threadIdx.x;
    const int wid = tid >> 5;
    const int lane = tid & 31;

    const int t0 = blockIdx.x * 128;
    const int n0 = blockIdx.y * 128;
    const int kbeg = (MODE == 0) ? 0 : (blockIdx.z * JCH);

    const __nv_bfloat16* Abase = (MODE == 0 ? g_Qc : g_Pc) + (size_t)t0 * LD + kbeg;
    const __nv_bfloat16* Bbase = (MODE == 0 ? g_Kc : g_VT) + (size_t)n0 * LD + kbeg;

    const uint32_t raw = su32(dsm_raw);
    const uint32_t sbase = (raw + 1023u) & ~1023u;

    const int wm = (wid & 3) * 32;       // warp M offset in tile
    const int wn = (wid >> 2) * 64;      // warp N offset in tile

    float acc[2][8][4];
#pragma unroll
    for (int mi = 0; mi < 2; mi++)
#pragma unroll
        for (int ni = 0; ni < 8; ni++)
#pragma unroll
            for (int q = 0; q < 4; q++) acc[mi][ni][q] = 0.0f;

    // ---- async copy of chunk c into stage (c % NSTAGE) ----
    auto issue = [&](int c) {
        const int s = c % NSTAGE;
        const uint32_t dA = sbase + s * STAGE_B;
        const uint32_t dB = dA + 16384;
        const int r = tid >> 1;                    // 0..127 (2 threads per row)
        const int q = (tid & 1) * 4;               // q..q+3 (16B each)
        const __nv_bfloat16* srcA = Abase + (size_t)r * LD + c * 64 + q * 8;
        const __nv_bfloat16* srcB = Bbase + (size_t)r * LD + c * 64 + q * 8;
#pragma unroll
        for (int j = 0; j < 4; j++) {
            cp16(dA + SWZ(r * 128 + (q + j) * 16), srcA + j * 8);
            cp16(dB + SWZ(r * 128 + (q + j) * 16), srcB + j * 8);
        }
        CP_COMMIT();
    };

    issue(0);
    issue(1);

    for (int c = 0; c < NCH; c++) {
        if (c + 1 < NCH) CP_WAIT1(); else CP_WAIT0();
        __syncthreads();
        // copy for c+2 in flight during the whole compute of c
        // (overwrites stage (c-1)%3 — drained: all warps passed this barrier
        //  only after finishing compute(c-1))
        if (c + 2 < NCH) issue(c + 2);

        const int s = c % NSTAGE;
        const uint32_t A = sbase + s * STAGE_B;
        const uint32_t B = A + 16384;

#pragma unroll
        for (int ks = 0; ks < 4; ks++) {
            // grouped loads: all 6 ldmatrix.x4 for this k16-step first,
            // then the 16 HMMAs — lets the scheduler overlap LDSM latency
            // with the previous step's MMA tail.
            uint32_t a[2][4];
            uint32_t b[4][4];
#pragma unroll
            for (int mi = 0; mi < 2; mi++) {
                int row = wm + 16 * mi + (lane & 15);
                int col = ks * 16 + (lane >> 4) * 8;
                ldsm4(a[mi][0], a[mi][1], a[mi][2], a[mi][3],
                      A + SWZ(row * 128 + col * 2));
            }
#pragma unroll
            for (int ni = 0; ni < 4; ni++) {
                int g = lane >> 3;                 // 0..3
                int row = wn + 16 * ni + (lane & 7) + ((g >> 1) * 8);
                int col = ks * 16 + (g & 1) * 8;
                ldsm4(b[ni][0], b[ni][1], b[ni][2], b[ni][3],
                      B + SWZ(row * 128 + col * 2));
            }
#pragma unroll
            for (int ni = 0; ni < 4; ni++)
#pragma unroll
                for (int mi = 0; mi < 2; mi++) {
                    mma16816(acc[mi][2 * ni],     a[mi][0], a[mi][1], a[mi][2], a[mi][3],
                             b[ni][0], b[ni][1]);
                    mma16816(acc[mi][2 * ni + 1], a[mi][0], a[mi][1], a[mi][2], a[mi][3],
                             b[ni][2], b[ni][3]);
                }
        }
    }

    // ---- epilogue: fragment layout m = t/4 (+8), n = 2*(t%4) ----
#pragma unroll
    for (int mi = 0; mi < 2; mi++)
#pragma unroll
        for (int ni = 0; ni < 8; ni++) {
            int m = t0 + wm + 16 * mi + (lane >> 2);
            int n = n0 + wn + 8 * ni + 2 * (lane & 3);
            float2 lo = make_float2(acc[mi][ni][0], acc[mi][ni][1]);
            float2 hi = make_float2(acc[mi][ni][2], acc[mi][ni][3]);
            if (MODE == 0) {
                if (n < UVOC) {
                    *(float2*)&g_S[(size_t)m * UVOC + n] = lo;
                    *(float2*)&g_S[(size_t)(m + 8) * UVOC + n] = hi;
                }
            } else {
                float* base = g_part + (size_t)blockIdx.z * T_TOK * EMB;
                *(float2*)&base[(size_t)m * EMB + n] = lo;
                *(float2*)&base[(size_t)(m + 8) * EMB + n] = hi;
            }
        }
}

// =========================================================================
// K3a: row max (pure fmax pass — no MUFU)
// =========================================================================
__global__ __launch_bounds__(256)
void k3a_max() {
    const int t = blockIdx.x;
    const float* row = g_S + (size_t)t * UVOC;
    const int tid = threadIdx.x;

    float m = -1e30f;
    for (int i = tid; i < UVOC / 4; i += 256) {
        float4 s4 = ((const float4*)row)[i];
        m = fmaxf(m, fmaxf(fmaxf(s4.x, s4.y), fmaxf(s4.z, s4.w)));
    }
#pragma unroll
    for (int off = 16; off > 0; off >>= 1)
        m = fmaxf(m, __shfl_xor_sync(0xffffffffu, m, off));
    __shared__ float wm[8];
    if ((tid & 31) == 0) wm[tid >> 5] = m;
    __syncthreads();
    if (tid == 0) {
        float M = wm[0];
#pragma unroll
        for (int w = 1; w < 8; w++) M = fmaxf(M, wm[w]);
        g_rowm[t] = M;
    }
}

// =========================================================================
// K3b: Pc = split(exp(S - m)) unnormalized; row sum -> g_rowl.
// =========================================================================
__global__ __launch_bounds__(256)
void k3b_exp() {
    const int t = blockIdx.x;
    const float* row = g_S + (size_t)t * UVOC;
    const int tid = threadIdx.x;
    const float bm = g_rowm[t];

    __nv_bfloat16* prow = g_Pc + (size_t)t * JPAD;
    float l = 0.0f;
    for (int i = tid; i < UVOC / 4; i += 256) {
        float4 s4 = ((const float4*)row)[i];
        float p0 = exp_fma(s4.x - bm);
        float p1 = exp_fma(s4.y - bm);
        float p2 = exp_fma(s4.z - bm);
        float p3 = exp_fma(s4.w - bm);
        l += (p0 + p1) + (p2 + p3);
        __nv_bfloat16 h0, l0, h1, l1, h2, l2, h3, l3;
        split32(p0, h0, l0); split32(p1, h1, l1);
        split32(p2, h2, l2); split32(p3, h3, l3);
        __nv_bfloat162 ha; ha.x = h0; ha.y = h1;
        __nv_bfloat162 hb; hb.x = h2; hb.y = h3;
        __nv_bfloat162 la; la.x = l0; la.y = l1;
        __nv_bfloat162 lb; lb.x = l2; lb.y = l3;
        int u = 4 * i;
        *(__nv_bfloat162*)(prow + u) = ha;
        *(__nv_bfloat162*)(prow + u + 2) = hb;
        *(__nv_bfloat162*)(prow + JSEG + u) = ha;
        *(__nv_bfloat162*)(prow + JSEG + u + 2) = hb;
        *(__nv_bfloat162*)(prow + 2 * JSEG + u) = la;
        *(__nv_bfloat162*)(prow + 2 * JSEG + u + 2) = lb;
    }
    // zero pad u in [UVOC, UPAD)
    __nv_bfloat162 z2; z2.x = __float2bfloat16(0.f); z2.y = __float2bfloat16(0.f);
    for (int u = UVOC + 2 * tid; u < UPAD; u += 512) {
        *(__nv_bfloat162*)(prow + u) = z2;
        *(__nv_bfloat162*)(prow + JSEG + u) = z2;
        *(__nv_bfloat162*)(prow + 2 * JSEG + u) = z2;
    }

#pragma unroll
    for (int off = 16; off > 0; off >>= 1)
        l += __shfl_xor_sync(0xffffffffu, l, off);
    __shared__ float wl[8];
    if ((tid & 31) == 0) wl[tid >> 5] = l;
    __syncthreads();
    if (tid == 0) {
        float L = wl[0];
#pragma unroll
        for (int w = 1; w < 8; w++) L += wl[w];
        g_rowl[t] = L;
    }
}

// =========================================================================
// K5: out = alpha*mono + (sum_z part[z]) / l[t]
// =========================================================================
__global__ __launch_bounds__(128)
void k5_combine(const int* __restrict__ tok,
                const float* __restrict__ memb,
                const float* __restrict__ aemb,
                float* __restrict__ out) {
    const int t = blockIdx.x;
    const int tid = threadIdx.x;
    const int tk = tok[t];
    const float al = aemb[tk];
    const float inv = 1.0f / g_rowl[t];

    float4 m4 = *(const float4*)&memb[(size_t)tk * EMB + 4 * tid];
    float4 s = make_float4(0.f, 0.f, 0.f, 0.f);
#pragma unroll
    for (int z = 0; z < ZSPLIT; z++) {
        float4 p = *(const float4*)&g_part[((size_t)z * T_TOK + t) * EMB + 4 * tid];
        s.x += p.x; s.y += p.y; s.z += p.z; s.w += p.w;
    }
    float4 o;
    o.x = al * m4.x + s.x * inv;
    o.y = al * m4.y + s.y * inv;
    o.z = al * m4.z + s.z * inv;
    o.w = al * m4.w + s.w * inv;
    *(float4*)&out[(size_t)t * EMB + 4 * tid] = o;
}

// =========================================================================
extern "C" void kernel_launch(void* const* d_in, const int* in_sizes, int n_in,
                              void* d_out, int out_size) {
    const int*   tok  = (const int*)d_in[0];
    const float* Tm   = (const float*)d_in[1];
    const float* qemb = (const float*)d_in[2];
    const float* memb = (const float*)d_in[3];
    const float* kemb = (const float*)d_in[4];
    const float* vemb = (const float*)d_in[5];
    const float* aemb = (const float*)d_in[6];
    float* out = (float*)d_out;

    cudaFuncSetAttribute(k1_prepq,  cudaFuncAttributeMaxDynamicSharedMemorySize, K1_SMEM);
    cudaFuncSetAttribute(k_gemm<0>, cudaFuncAttributeMaxDynamicSharedMemorySize, GSM);
    cudaFuncSetAttribute(k_gemm<1>, cudaFuncAttributeMaxDynamicSharedMemorySize, GSM);

    // prologue: query transform + bf16 split/concat tables
    k1_prepq<<<dim3(T_TOK / 64, EMB / 128), 128, K1_SMEM>>>(tok, qemb, Tm);
    k_convK<<<(UPAD * (EMB / 4) + 255) / 256, 256>>>(kemb);
    k_convV<<<dim3(UPAD / 64, EMB / 64), 256>>>(vemb);

    // GEMM1: S = Qc * Kc^T (x fastest = t-tiles -> Kc tile L2 co-residency)
    k_gemm<0><<<dim3(T_TOK / 128, UPAD / 128), 256, GSM>>>();

    // softmax: max pass, then exp + split (unnormalized)
    k3a_max<<<T_TOK, 256>>>();
    k3b_exp<<<T_TOK, 256>>>();

    // GEMM2: part[z] = Pc * VT^T
    k_gemm<1><<<dim3(T_TOK / 128, EMB / 128, ZSPLIT), 256, GSM>>>();

    // combine (normalize here)
    k5_combine<<<T_TOK, 128>>>(tok, memb, aemb, out);
}